// round 4
// baseline (speedup 1.0000x reference)
#include <cuda_runtime.h>

#define IN_F   5
#define D_FC   32
#define D_H    64
#define NG     256      // 4*D_H gate rows
#define T_LEN  512
#define B_TOT  4096
#define NBLK   296      // 148 SMs * occupancy 2, single balanced wave
#define BLOCK  256
#define CHUNK  16       // x staging chunk (timesteps)
#define NB_MAX 14       // max batch elements per block (248 blocks get 14, 48 get 13)

// Precomputed fused input projection: W_comb [256][5], bias_comb [256]
__device__ float g_Wc[NG * IN_F];
__device__ float g_bc[NG];

// ---------------------------------------------------------------------------
// Setup kernel: fold fc0 into the LSTM input projection.
//   W_comb = W_ih @ W0          (256x32 @ 32x5 -> 256x5)
//   bias_c = W_ih @ b0 + b_ih + b_hh
// ---------------------------------------------------------------------------
__global__ void precompute_kernel(const float* __restrict__ W0,
                                  const float* __restrict__ b0,
                                  const float* __restrict__ W_ih,
                                  const float* __restrict__ b_ih,
                                  const float* __restrict__ b_hh)
{
    int r = blockIdx.x * blockDim.x + threadIdx.x;
    if (r >= NG) return;
    float wc[IN_F] = {0.f, 0.f, 0.f, 0.f, 0.f};
    float bc = b_ih[r] + b_hh[r];
    for (int m = 0; m < D_FC; ++m) {
        float wim = W_ih[r * D_FC + m];
        bc += wim * b0[m];
        #pragma unroll
        for (int k = 0; k < IN_F; ++k)
            wc[k] += wim * W0[m * IN_F + k];
    }
    #pragma unroll
    for (int k = 0; k < IN_F; ++k) g_Wc[r * IN_F + k] = wc[k];
    g_bc[r] = bc;
}

// ---------------------------------------------------------------------------
// Packed f32x2 FMA (Blackwell FFMA2) + helpers
// ---------------------------------------------------------------------------
__device__ __forceinline__ unsigned long long fma2(unsigned long long a,
                                                   unsigned long long b,
                                                   unsigned long long c)
{
    unsigned long long d;
    asm("fma.rn.f32x2 %0, %1, %2, %3;" : "=l"(d) : "l"(a), "l"(b), "l"(c));
    return d;
}

__device__ __forceinline__ float2 u2f2(unsigned long long v)
{
    float2 r;
    asm("mov.b64 {%0, %1}, %2;" : "=f"(r.x), "=f"(r.y) : "l"(v));
    return r;
}

__device__ __forceinline__ float sigmoid_(float x)
{
    // 1 / (1 + e^-x): MUFU.EX2 + MUFU.RCP, ~2ulp
    return __fdividef(1.f, 1.f + __expf(-x));
}

__device__ __forceinline__ float tanh_(float x)
{
    // 2/(1+e^{-2x}) - 1; saturates correctly for |x| large
    float e = __expf(-2.f * x);
    return __fdividef(2.f, 1.f + e) - 1.f;
}

// ---------------------------------------------------------------------------
// Fused persistent LSTM kernel.
//   Thread tid owns gate row r=tid: W_hh[r][0:64] lives in 32 packed f32x2
//   registers. Per step: phase1 computes gates for all local batches
//   (broadcast LDS of h), phase2 applies nonlinearities & updates h/c.
// ---------------------------------------------------------------------------
__global__ void __launch_bounds__(BLOCK, 2)
lstm_kernel(const float* __restrict__ x,
            const float* __restrict__ W_hh,
            const float* __restrict__ Wo,
            const float* __restrict__ bo,
            float* __restrict__ out)
{
    __shared__ __align__(16) float h_sh[NB_MAX * D_H];            // 3.5 KB
    __shared__ float gates_sh[NB_MAX * NG];                        // 14 KB
    __shared__ __align__(16) float x_sh[NB_MAX * CHUNK * IN_F];    // 4.4 KB
    __shared__ float wo_sh[D_H];

    const int tid = threadIdx.x;
    const int bid = blockIdx.x;

    // batch partition: 248 blocks * 14 + 48 blocks * 13 = 4096
    int nb, b0g;
    if (bid < 248) { nb = 14; b0g = bid * 14; }
    else           { nb = 13; b0g = 248 * 14 + (bid - 248) * 13; }

    // register-resident W_hh row (packed pairs) + fused input weights
    const int r = tid;
    unsigned long long w[D_H / 2];
    {
        const unsigned long long* wp =
            (const unsigned long long*)(W_hh + r * D_H);
        #pragma unroll
        for (int i = 0; i < D_H / 2; ++i) w[i] = wp[i];
    }
    float wc[IN_F];
    #pragma unroll
    for (int k = 0; k < IN_F; ++k) wc[k] = g_Wc[r * IN_F + k];
    const float bc = g_bc[r];

    if (tid < D_H) wo_sh[tid] = Wo[tid];
    for (int i = tid; i < NB_MAX * D_H; i += BLOCK) h_sh[i] = 0.f;

    float creg[4] = {0.f, 0.f, 0.f, 0.f};  // cell state: units tid+256*s
    __syncthreads();

    for (int t = 0; t < T_LEN; ++t) {
        // ---- stage x chunk (every CHUNK steps); previous chunk fully
        //      consumed before last barrier, so no extra sync needed before
        if ((t & (CHUNK - 1)) == 0) {
            #pragma unroll 1
            for (int i = tid; i < NB_MAX * 20; i += BLOCK) {
                int b = i / 20, j = i - b * 20;
                int gb = b0g + b;
                if (gb > B_TOT - 1) gb = B_TOT - 1;  // clamp (data unused)
                const float4* src =
                    (const float4*)(x + ((long long)gb * T_LEN + t) * IN_F);
                ((float4*)x_sh)[b * 20 + j] = src[j];
            }
            __syncthreads();
        }

        const int toff = (t & (CHUNK - 1)) * IN_F;

        // ---- phase 1: gates[b][r] = bias + Wc@x + Whh@h  (FFMA2 inner loop)
        #pragma unroll
        for (int b = 0; b < NB_MAX; ++b) {
            const ulonglong2* hp = (const ulonglong2*)(h_sh + b * D_H);
            unsigned long long a0 = 0ull, a1 = 0ull;  // packed (0,0)
            #pragma unroll
            for (int i = 0; i < 16; ++i) {
                ulonglong2 hv = hp[i];                 // broadcast LDS.128
                a0 = fma2(w[2 * i],     hv.x, a0);
                a1 = fma2(w[2 * i + 1], hv.y, a1);
            }
            const float* xb = x_sh + b * (CHUNK * IN_F) + toff;
            float acc = bc;
            #pragma unroll
            for (int k = 0; k < IN_F; ++k)
                acc = __fmaf_rn(wc[k], xb[k], acc);
            float2 f0 = u2f2(a0), f1 = u2f2(a1);
            acc += (f0.x + f1.x) + (f0.y + f1.y);
            gates_sh[b * NG + r] = acc;
        }
        __syncthreads();

        // ---- phase 2: nonlinearities + state update (PyTorch gate order i,f,g,o)
        #pragma unroll
        for (int s = 0; s < 4; ++s) {
            int u = tid + BLOCK * s;
            if (u < nb * D_H) {
                int b = u >> 6, j = u & 63;
                const float* gp = gates_sh + b * NG + j;
                float iv = sigmoid_(gp[0]);
                float fv = sigmoid_(gp[64]);
                float gv = tanh_(gp[128]);
                float ov = sigmoid_(gp[192]);
                float cc = __fmaf_rn(fv, creg[s], iv * gv);
                creg[s] = cc;
                h_sh[u] = ov * tanh_(cc);
            }
        }
        __syncthreads();
    }

    // ---- output: out[b] = Wo @ h_last + bo
    if (tid < nb) {
        float acc = bo[0];
        #pragma unroll
        for (int j = 0; j < D_H; ++j)
            acc = __fmaf_rn(wo_sh[j], h_sh[tid * D_H + j], acc);
        out[b0g + tid] = acc;
    }
}

// ---------------------------------------------------------------------------
// Harness entry. Inputs (metadata order):
//   0:x 1:W0 2:b0 3:W_ih 4:W_hh 5:b_ih 6:b_hh 7:Wo 8:bo ; out: float[4096]
// ---------------------------------------------------------------------------
extern "C" void kernel_launch(void* const* d_in, const int* in_sizes, int n_in,
                              void* d_out, int out_size)
{
    (void)in_sizes; (void)n_in; (void)out_size;
    const float* x    = (const float*)d_in[0];
    const float* W0   = (const float*)d_in[1];
    const float* b0   = (const float*)d_in[2];
    const float* W_ih = (const float*)d_in[3];
    const float* W_hh = (const float*)d_in[4];
    const float* b_ih = (const float*)d_in[5];
    const float* b_hh = (const float*)d_in[6];
    const float* Wo   = (const float*)d_in[7];
    const float* bo   = (const float*)d_in[8];

    precompute_kernel<<<1, NG>>>(W0, b0, W_ih, b_ih, b_hh);
    lstm_kernel<<<NBLK, BLOCK>>>(x, W_hh, Wo, bo, (float*)d_out);
}

// round 7
// speedup vs baseline: 1.0742x; 1.0742x over previous
#include <cuda_runtime.h>

#define IN_F   5
#define D_FC   32
#define D_H    64
#define NG     256      // 4*D_H gate rows
#define T_LEN  512
#define B_TOT  4096
#define NBLK   296      // 148 SMs * 2 blocks, single balanced wave
#define BLOCK  128      // each thread owns 2 gate rows
#define CHUNK  16       // x staging chunk (timesteps)
#define NB_MAX 14       // 248 blocks get 14 batches, 48 get 13
#define XPAD   6        // x padded to 6 floats per timestep (u64-aligned)

// Precomputed fused input projection: W_comb [256][5], bias_comb [256]
__device__ float g_Wc[NG * IN_F];
__device__ float g_bc[NG];

// ---------------------------------------------------------------------------
// Setup: fold fc0 into LSTM input projection.
//   W_comb = W_ih @ W0 ; bias_c = W_ih @ b0 + b_ih + b_hh
// ---------------------------------------------------------------------------
__global__ void precompute_kernel(const float* __restrict__ W0,
                                  const float* __restrict__ b0,
                                  const float* __restrict__ W_ih,
                                  const float* __restrict__ b_ih,
                                  const float* __restrict__ b_hh)
{
    int r = blockIdx.x * blockDim.x + threadIdx.x;
    if (r >= NG) return;
    float wc[IN_F] = {0.f, 0.f, 0.f, 0.f, 0.f};
    float bc = b_ih[r] + b_hh[r];
    for (int m = 0; m < D_FC; ++m) {
        float wim = W_ih[r * D_FC + m];
        bc += wim * b0[m];
        #pragma unroll
        for (int k = 0; k < IN_F; ++k)
            wc[k] += wim * W0[m * IN_F + k];
    }
    #pragma unroll
    for (int k = 0; k < IN_F; ++k) g_Wc[r * IN_F + k] = wc[k];
    g_bc[r] = bc;
}

// ---------------------------------------------------------------------------
// Packed f32x2 helpers (Blackwell FFMA2 path)
// ---------------------------------------------------------------------------
__device__ __forceinline__ unsigned long long fma2(unsigned long long a,
                                                   unsigned long long b,
                                                   unsigned long long c)
{
    unsigned long long d;
    asm("fma.rn.f32x2 %0, %1, %2, %3;" : "=l"(d) : "l"(a), "l"(b), "l"(c));
    return d;
}

__device__ __forceinline__ unsigned long long add2(unsigned long long a,
                                                   unsigned long long b)
{
    unsigned long long d;
    asm("add.rn.f32x2 %0, %1, %2;" : "=l"(d) : "l"(a), "l"(b));
    return d;
}

__device__ __forceinline__ float2 u2f2(unsigned long long v)
{
    float2 r;
    asm("mov.b64 {%0, %1}, %2;" : "=f"(r.x), "=f"(r.y) : "l"(v));
    return r;
}

__device__ __forceinline__ unsigned long long pack2(float lo, float hi)
{
    unsigned long long v;
    asm("mov.b64 %0, {%1, %2};" : "=l"(v) : "f"(lo), "f"(hi));
    return v;
}

__device__ __forceinline__ float sigmoid_(float x)
{
    return __fdividef(1.f, 1.f + __expf(-x));
}

__device__ __forceinline__ float tanh_(float x)
{
    float e = __expf(-2.f * x);
    return __fdividef(2.f, 1.f + e) - 1.f;
}

// ---------------------------------------------------------------------------
// Fused persistent LSTM kernel, 2 gate rows per thread.
//   half==0 threads own rows (j, j+128)  = (i, g) -> emit sigmoid(i)*tanh(g)
//   half==1 threads own rows (j+64,j+192)= (f, o) -> emit sigmoid(f),sigmoid(o)
//   Phase 2 (tiny): c = sf*c + a ; h = so*tanh(c)
// ---------------------------------------------------------------------------
__global__ void __launch_bounds__(BLOCK, 2)
lstm_kernel(const float* __restrict__ x,
            const float* __restrict__ W_hh,
            const float* __restrict__ Wo,
            const float* __restrict__ bo,
            float* __restrict__ out)
{
    __shared__ __align__(16) float h_sh[NB_MAX * D_H];              // 3.5 KB
    __shared__ float aig_sh[NB_MAX * D_H];                           // 3.5 KB
    __shared__ float sf_sh[NB_MAX * D_H];                            // 3.5 KB
    __shared__ float so_sh[NB_MAX * D_H];                            // 3.5 KB
    __shared__ __align__(16) float x_sh[NB_MAX * CHUNK * XPAD];      // 5.25 KB
    __shared__ float wo_sh[D_H];

    const int tid  = threadIdx.x;
    const int bid  = blockIdx.x;
    const int rg   = tid & 63;
    const int half = tid >> 6;

    // batch partition: 248 blocks * 14 + 48 blocks * 13 = 4096
    int nb, b0g;
    if (bid < 248) { nb = 14; b0g = bid * 14; }
    else           { nb = 13; b0g = 248 * 14 + (bid - 248) * 13; }

    // rows owned by this thread
    const int r0 = half ? (rg + 64)  : rg;          // f : i
    const int r1 = half ? (rg + 192) : (rg + 128);  // o : g

    // register-resident W_hh rows (packed f32x2 pairs)
    unsigned long long w0[D_H / 2], w1[D_H / 2];
    {
        const unsigned long long* p0 = (const unsigned long long*)(W_hh + r0 * D_H);
        const unsigned long long* p1 = (const unsigned long long*)(W_hh + r1 * D_H);
        #pragma unroll
        for (int i = 0; i < D_H / 2; ++i) { w0[i] = p0[i]; w1[i] = p1[i]; }
    }

    // fused input weights, packed (x padded to 6 -> 3 pairs, last hi = 0)
    unsigned long long wc0[3], wc1[3];
    {
        const float* a = g_Wc + r0 * IN_F;
        const float* b = g_Wc + r1 * IN_F;
        wc0[0] = pack2(a[0], a[1]); wc0[1] = pack2(a[2], a[3]); wc0[2] = pack2(a[4], 0.f);
        wc1[0] = pack2(b[0], b[1]); wc1[1] = pack2(b[2], b[3]); wc1[2] = pack2(b[4], 0.f);
    }
    const unsigned long long bc0 = pack2(g_bc[r0], 0.f);
    const unsigned long long bc1 = pack2(g_bc[r1], 0.f);

    if (tid < D_H) wo_sh[tid] = Wo[tid];
    #pragma unroll
    for (int i = tid; i < NB_MAX * D_H; i += BLOCK) h_sh[i] = 0.f;
    for (int i = tid; i < NB_MAX * CHUNK * XPAD; i += BLOCK) x_sh[i] = 0.f; // pads

    float creg[7] = {0.f, 0.f, 0.f, 0.f, 0.f, 0.f, 0.f};  // cell: u = tid+128*s
    __syncthreads();

    for (int t = 0; t < T_LEN; ++t) {
        // ---- stage x chunk (previous chunk fully consumed: barrier after
        //      phase1 of t-1 already passed)
        if ((t & (CHUNK - 1)) == 0) {
            #pragma unroll 1
            for (int i = tid; i < NB_MAX * CHUNK * IN_F; i += BLOCK) {
                int b  = i / (CHUNK * IN_F);
                int rm = i - b * (CHUNK * IN_F);
                int tt = rm / IN_F;
                int k  = rm - tt * IN_F;
                int gb = b0g + b;
                if (gb > B_TOT - 1) gb = B_TOT - 1;   // clamp (data unused)
                x_sh[(b * CHUNK + tt) * XPAD + k] =
                    x[((long long)gb * T_LEN + t + tt) * IN_F + k];
            }
            __syncthreads();
        }

        const int tslot = t & (CHUNK - 1);

        // ---- phase 1: two gate dots per thread + early nonlinearities
        #pragma unroll 2
        for (int b = 0; b < NB_MAX; ++b) {
            const ulonglong2* hp = (const ulonglong2*)(h_sh + b * D_H);
            const unsigned long long* xp =
                (const unsigned long long*)(x_sh + (b * CHUNK + tslot) * XPAD);
            unsigned long long xv0 = xp[0], xv1 = xp[1], xv2 = xp[2];

            unsigned long long a00 = bc0, a01 = 0ull;
            unsigned long long a10 = bc1, a11 = 0ull;
            a00 = fma2(wc0[0], xv0, a00);
            a10 = fma2(wc1[0], xv0, a10);
            a01 = fma2(wc0[1], xv1, a01);
            a11 = fma2(wc1[1], xv1, a11);
            a00 = fma2(wc0[2], xv2, a00);
            a10 = fma2(wc1[2], xv2, a10);

            #pragma unroll
            for (int i = 0; i < 16; ++i) {
                ulonglong2 hv = hp[i];                 // broadcast LDS.128
                a00 = fma2(w0[2 * i],     hv.x, a00);
                a10 = fma2(w1[2 * i],     hv.x, a10);
                a01 = fma2(w0[2 * i + 1], hv.y, a01);
                a11 = fma2(w1[2 * i + 1], hv.y, a11);
            }
            a00 = add2(a00, a01);
            a10 = add2(a10, a11);
            float2 f0 = u2f2(a00);
            float2 f1 = u2f2(a10);
            float acc0 = f0.x + f0.y;
            float acc1 = f1.x + f1.y;

            if (half == 0) {   // (i, g) -> i*g contribution
                aig_sh[b * D_H + rg] = sigmoid_(acc0) * tanh_(acc1);
            } else {           // (f, o)
                sf_sh[b * D_H + rg] = sigmoid_(acc0);
                so_sh[b * D_H + rg] = sigmoid_(acc1);
            }
        }
        __syncthreads();

        // ---- phase 2: state update (cheap: 1 tanh per unit)
        #pragma unroll
        for (int s = 0; s < 7; ++s) {
            int u = tid + BLOCK * s;
            if (u < nb * D_H) {
                float a  = aig_sh[u];
                float sf = sf_sh[u];
                float so = so_sh[u];
                float cc = __fmaf_rn(sf, creg[s], a);
                creg[s] = cc;
                h_sh[u] = so * tanh_(cc);
            }
        }
        __syncthreads();
    }

    // ---- output: out[b] = Wo @ h_last + bo
    if (tid < nb) {
        float acc = bo[0];
        #pragma unroll
        for (int j = 0; j < D_H; ++j)
            acc = __fmaf_rn(wo_sh[j], h_sh[tid * D_H + j], acc);
        out[b0g + tid] = acc;
    }
}

// ---------------------------------------------------------------------------
// Harness entry. Inputs (metadata order):
//   0:x 1:W0 2:b0 3:W_ih 4:W_hh 5:b_ih 6:b_hh 7:Wo 8:bo ; out: float[4096]
// ---------------------------------------------------------------------------
extern "C" void kernel_launch(void* const* d_in, const int* in_sizes, int n_in,
                              void* d_out, int out_size)
{
    (void)in_sizes; (void)n_in; (void)out_size;
    const float* x    = (const float*)d_in[0];
    const float* W0   = (const float*)d_in[1];
    const float* b0   = (const float*)d_in[2];
    const float* W_ih = (const float*)d_in[3];
    const float* W_hh = (const float*)d_in[4];
    const float* b_ih = (const float*)d_in[5];
    const float* b_hh = (const float*)d_in[6];
    const float* Wo   = (const float*)d_in[7];
    const float* bo   = (const float*)d_in[8];

    precompute_kernel<<<1, NG>>>(W0, b0, W_ih, b_ih, b_hh);
    lstm_kernel<<<NBLK, BLOCK>>>(x, W_hh, Wo, bo, (float*)d_out);
}

// round 8
// speedup vs baseline: 1.1662x; 1.0857x over previous
#include <cuda_runtime.h>

#define IN_F   5
#define D_FC   32
#define D_H    64
#define NG     256      // 4*D_H gate rows
#define T_LEN  512
#define B_TOT  4096
#define NBLK   444      // 148 SMs * 3 blocks, single wave
#define BLOCK  128      // each thread owns 2 gate rows
#define CHUNK  16       // x staging chunk (timesteps)
#define NB_MAX 10       // 100 blocks get 10 batches, 344 get 9
#define XPAD   6        // x padded to 6 floats per timestep (u64-aligned)

// Precomputed fused input projection: W_comb [256][5], bias_comb [256]
__device__ float g_Wc[NG * IN_F];
__device__ float g_bc[NG];

// ---------------------------------------------------------------------------
// Setup: fold fc0 into LSTM input projection.
//   W_comb = W_ih @ W0 ; bias_c = W_ih @ b0 + b_ih + b_hh
// ---------------------------------------------------------------------------
__global__ void precompute_kernel(const float* __restrict__ W0,
                                  const float* __restrict__ b0,
                                  const float* __restrict__ W_ih,
                                  const float* __restrict__ b_ih,
                                  const float* __restrict__ b_hh)
{
    int r = blockIdx.x * blockDim.x + threadIdx.x;
    if (r >= NG) return;
    float wc[IN_F] = {0.f, 0.f, 0.f, 0.f, 0.f};
    float bc = b_ih[r] + b_hh[r];
    for (int m = 0; m < D_FC; ++m) {
        float wim = W_ih[r * D_FC + m];
        bc += wim * b0[m];
        #pragma unroll
        for (int k = 0; k < IN_F; ++k)
            wc[k] += wim * W0[m * IN_F + k];
    }
    #pragma unroll
    for (int k = 0; k < IN_F; ++k) g_Wc[r * IN_F + k] = wc[k];
    g_bc[r] = bc;
}

// ---------------------------------------------------------------------------
// Packed f32x2 helpers (Blackwell FFMA2 path)
// ---------------------------------------------------------------------------
__device__ __forceinline__ unsigned long long fma2(unsigned long long a,
                                                   unsigned long long b,
                                                   unsigned long long c)
{
    unsigned long long d;
    asm("fma.rn.f32x2 %0, %1, %2, %3;" : "=l"(d) : "l"(a), "l"(b), "l"(c));
    return d;
}

__device__ __forceinline__ unsigned long long add2(unsigned long long a,
                                                   unsigned long long b)
{
    unsigned long long d;
    asm("add.rn.f32x2 %0, %1, %2;" : "=l"(d) : "l"(a), "l"(b));
    return d;
}

__device__ __forceinline__ float2 u2f2(unsigned long long v)
{
    float2 r;
    asm("mov.b64 {%0, %1}, %2;" : "=f"(r.x), "=f"(r.y) : "l"(v));
    return r;
}

__device__ __forceinline__ unsigned long long pack2(float lo, float hi)
{
    unsigned long long v;
    asm("mov.b64 %0, {%1, %2};" : "=l"(v) : "f"(lo), "f"(hi));
    return v;
}

__device__ __forceinline__ float sigmoid_(float x)
{
    return __fdividef(1.f, 1.f + __expf(-x));
}

__device__ __forceinline__ float tanh_(float x)
{
    float e = __expf(-2.f * x);
    return __fdividef(2.f, 1.f + e) - 1.f;
}

// ---------------------------------------------------------------------------
// Fused persistent LSTM kernel, 2 gate rows per thread, 3 blocks/SM.
//   half==0 threads own rows (j, j+128)  = (i, g) -> emit sigmoid(i)*tanh(g)
//   half==1 threads own rows (j+64,j+192)= (f, o) -> emit sigmoid(f),sigmoid(o)
//   Phase 2 (tiny): c = sf*c + a ; h = so*tanh(c)   (c lives in smem)
// ---------------------------------------------------------------------------
__global__ void __launch_bounds__(BLOCK, 3)
lstm_kernel(const float* __restrict__ x,
            const float* __restrict__ W_hh,
            const float* __restrict__ Wo,
            const float* __restrict__ bo,
            float* __restrict__ out)
{
    __shared__ __align__(16) float h_sh[NB_MAX * D_H];              // 2.5 KB
    __shared__ float c_sh[NB_MAX * D_H];                             // 2.5 KB
    __shared__ float aig_sh[NB_MAX * D_H];                           // 2.5 KB
    __shared__ float sf_sh[NB_MAX * D_H];                            // 2.5 KB
    __shared__ float so_sh[NB_MAX * D_H];                            // 2.5 KB
    __shared__ __align__(16) float x_sh[NB_MAX * CHUNK * XPAD];      // 3.75 KB
    __shared__ float wo_sh[D_H];

    const int tid  = threadIdx.x;
    const int bid  = blockIdx.x;
    const int rg   = tid & 63;
    const int half = tid >> 6;

    // batch partition: 100 blocks * 10 + 344 blocks * 9 = 4096
    int nb, b0g;
    if (bid < 100) { nb = 10; b0g = bid * 10; }
    else           { nb = 9;  b0g = 1000 + (bid - 100) * 9; }

    // rows owned by this thread
    const int r0 = half ? (rg + 64)  : rg;          // f : i
    const int r1 = half ? (rg + 192) : (rg + 128);  // o : g

    // register-resident W_hh rows (packed f32x2 pairs)
    unsigned long long w0[D_H / 2], w1[D_H / 2];
    {
        const unsigned long long* p0 = (const unsigned long long*)(W_hh + r0 * D_H);
        const unsigned long long* p1 = (const unsigned long long*)(W_hh + r1 * D_H);
        #pragma unroll
        for (int i = 0; i < D_H / 2; ++i) { w0[i] = p0[i]; w1[i] = p1[i]; }
    }

    // fused input weights, packed (x padded to 6 -> 3 pairs, last hi = 0)
    unsigned long long wc0[3], wc1[3];
    {
        const float* a = g_Wc + r0 * IN_F;
        const float* b = g_Wc + r1 * IN_F;
        wc0[0] = pack2(a[0], a[1]); wc0[1] = pack2(a[2], a[3]); wc0[2] = pack2(a[4], 0.f);
        wc1[0] = pack2(b[0], b[1]); wc1[1] = pack2(b[2], b[3]); wc1[2] = pack2(b[4], 0.f);
    }
    const unsigned long long bc0 = pack2(g_bc[r0], 0.f);
    const unsigned long long bc1 = pack2(g_bc[r1], 0.f);

    if (tid < D_H) wo_sh[tid] = Wo[tid];
    #pragma unroll
    for (int i = tid; i < NB_MAX * D_H; i += BLOCK) { h_sh[i] = 0.f; c_sh[i] = 0.f; }
    for (int i = tid; i < NB_MAX * CHUNK * XPAD; i += BLOCK) x_sh[i] = 0.f; // pads

    __syncthreads();

    for (int t = 0; t < T_LEN; ++t) {
        // ---- stage x chunk (previous chunk fully consumed before this point)
        if ((t & (CHUNK - 1)) == 0) {
            #pragma unroll 1
            for (int i = tid; i < NB_MAX * CHUNK * IN_F; i += BLOCK) {
                int b  = i / (CHUNK * IN_F);
                int rm = i - b * (CHUNK * IN_F);
                int tt = rm / IN_F;
                int k  = rm - tt * IN_F;
                int gb = b0g + b;
                if (gb > B_TOT - 1) gb = B_TOT - 1;   // clamp (data unused)
                x_sh[(b * CHUNK + tt) * XPAD + k] =
                    x[((long long)gb * T_LEN + t + tt) * IN_F + k];
            }
            __syncthreads();
        }

        const int tslot = t & (CHUNK - 1);

        // ---- phase 1: two gate dots per thread + early nonlinearities
        #pragma unroll 1
        for (int b = 0; b < nb; ++b) {
            const ulonglong2* hp = (const ulonglong2*)(h_sh + b * D_H);
            const unsigned long long* xp =
                (const unsigned long long*)(x_sh + (b * CHUNK + tslot) * XPAD);
            unsigned long long xv0 = xp[0], xv1 = xp[1], xv2 = xp[2];

            unsigned long long a00 = bc0, a01 = 0ull;
            unsigned long long a10 = bc1, a11 = 0ull;
            a00 = fma2(wc0[0], xv0, a00);
            a10 = fma2(wc1[0], xv0, a10);
            a01 = fma2(wc0[1], xv1, a01);
            a11 = fma2(wc1[1], xv1, a11);
            a00 = fma2(wc0[2], xv2, a00);
            a10 = fma2(wc1[2], xv2, a10);

            #pragma unroll
            for (int i = 0; i < 16; ++i) {
                ulonglong2 hv = hp[i];                 // broadcast LDS.128
                a00 = fma2(w0[2 * i],     hv.x, a00);
                a10 = fma2(w1[2 * i],     hv.x, a10);
                a01 = fma2(w0[2 * i + 1], hv.y, a01);
                a11 = fma2(w1[2 * i + 1], hv.y, a11);
            }
            a00 = add2(a00, a01);
            a10 = add2(a10, a11);
            float2 f0 = u2f2(a00);
            float2 f1 = u2f2(a10);
            float acc0 = f0.x + f0.y;
            float acc1 = f1.x + f1.y;

            if (half == 0) {   // (i, g) -> i*g contribution
                aig_sh[b * D_H + rg] = sigmoid_(acc0) * tanh_(acc1);
            } else {           // (f, o)
                sf_sh[b * D_H + rg] = sigmoid_(acc0);
                so_sh[b * D_H + rg] = sigmoid_(acc1);
            }
        }
        __syncthreads();

        // ---- phase 2: state update (cheap: 1 tanh per unit, c in smem)
        #pragma unroll
        for (int s = 0; s < (NB_MAX * D_H + BLOCK - 1) / BLOCK; ++s) {
            int u = tid + BLOCK * s;
            if (u < nb * D_H) {
                float a  = aig_sh[u];
                float sf = sf_sh[u];
                float so = so_sh[u];
                float cc = __fmaf_rn(sf, c_sh[u], a);
                c_sh[u] = cc;
                h_sh[u] = so * tanh_(cc);
            }
        }
        __syncthreads();
    }

    // ---- output: out[b] = Wo @ h_last + bo
    if (tid < nb) {
        float acc = bo[0];
        #pragma unroll
        for (int j = 0; j < D_H; ++j)
            acc = __fmaf_rn(wo_sh[j], h_sh[tid * D_H + j], acc);
        out[b0g + tid] = acc;
    }
}

// ---------------------------------------------------------------------------
// Harness entry. Inputs (metadata order):
//   0:x 1:W0 2:b0 3:W_ih 4:W_hh 5:b_ih 6:b_hh 7:Wo 8:bo ; out: float[4096]
// ---------------------------------------------------------------------------
extern "C" void kernel_launch(void* const* d_in, const int* in_sizes, int n_in,
                              void* d_out, int out_size)
{
    (void)in_sizes; (void)n_in; (void)out_size;
    const float* x    = (const float*)d_in[0];
    const float* W0   = (const float*)d_in[1];
    const float* b0   = (const float*)d_in[2];
    const float* W_ih = (const float*)d_in[3];
    const float* W_hh = (const float*)d_in[4];
    const float* b_ih = (const float*)d_in[5];
    const float* b_hh = (const float*)d_in[6];
    const float* Wo   = (const float*)d_in[7];
    const float* bo   = (const float*)d_in[8];

    precompute_kernel<<<1, NG>>>(W0, b0, W_ih, b_ih, b_hh);
    lstm_kernel<<<NBLK, BLOCK>>>(x, W_hh, Wo, bo, (float*)d_out);
}